// round 9
// baseline (speedup 1.0000x reference)
#include <cuda_runtime.h>

// Problem constants (fixed by the dataset)
#define B_TOTAL   131072
#define S_DIM     17
#define A_DIM     7
#define DPHI      128
#define DPSI      8

#define NPART     32                  // partial-C blocks
#define I_PER     (DPHI / NPART)      // 4 i-values per block
#define CPS       136                 // padded [17][8] floats per partial
#define CPS4      34                  // ... as float4

#define TILE      256                 // samples per k_main block
#define NBLK_MAIN (B_TOTAL / TILE)    // 512 blocks

// Per-block partial C matrices, padded [17][8] (pad col written as 0).
__device__ float g_Cpart[NPART * CPS];

// ---------------------------------------------------------------------------
// Kernel 1: block p computes partial C over i in [p*I_PER,(p+1)*I_PER).
// 512 threads: 4 threads per (s,a), 32 j-iters each, 2 independent inner
// accumulator chains -> ~4x shorter serial FMA chain than the 256-thr form.
// Implicit PDL completion trigger covers the g_Cpart writes.
// ---------------------------------------------------------------------------
__global__ __launch_bounds__(512)
void k_partialC(const float* __restrict__ Wphi,   // [128,17]
                const float* __restrict__ Wpsi,   // [8,7]
                const float* __restrict__ K,      // [128,128,8]
                const float* __restrict__ wlin)   // [1,128]
{
    __shared__ float Msm[DPHI * DPSI];   // 1024 floats, layout j*8+z
    __shared__ float Ctmp[512];

    const int p   = blockIdx.x;
    const int tid = threadIdx.x;         // 512 threads

    // --- M partial: threads 0..255 own one float4 of the 1024 floats ---
    if (tid < 256) {
        const float4* K4 = reinterpret_cast<const float4*>(K);
        float4 acc = make_float4(0.f, 0.f, 0.f, 0.f);
#pragma unroll
        for (int ii = 0; ii < I_PER; ii++) {
            const int i = p * I_PER + ii;
            const float w = __ldg(&wlin[i]);
            const float4 kv = K4[i * 256 + tid];
            acc.x = fmaf(w, kv.x, acc.x);
            acc.y = fmaf(w, kv.y, acc.y);
            acc.z = fmaf(w, kv.z, acc.z);
            acc.w = fmaf(w, kv.w, acc.w);
        }
        reinterpret_cast<float4*>(Msm)[tid] = acc;
    }
    __syncthreads();

    // --- C partial: 4 threads per (s,a), 32 j-iters each ---
    float c = 0.f;
    if (tid < 4 * S_DIM * A_DIM) {       // 476 active threads
        const int o = tid >> 2;
        const int q = tid & 3;
        const int s = o / A_DIM;
        const int a = o - s * A_DIM;

        float psi[DPSI];
#pragma unroll
        for (int z = 0; z < DPSI; z++) psi[z] = __ldg(&Wpsi[z * A_DIM + a]);

        const int j0 = q * 32;
        float c0 = 0.f, c1 = 0.f;        // 2 independent outer chains
#pragma unroll 4
        for (int jl = 0; jl < 32; jl += 2) {
            const int j = j0 + jl;
            // 2 independent inner chains per j (z split 0-3 / 4-7)
            float iA0 = 0.f, iA1 = 0.f, iB0 = 0.f, iB1 = 0.f;
#pragma unroll
            for (int z = 0; z < 4; z++) {
                iA0 = fmaf(Msm[j * DPSI + z],           psi[z],     iA0);
                iA1 = fmaf(Msm[j * DPSI + 4 + z],       psi[4 + z], iA1);
                iB0 = fmaf(Msm[(j + 1) * DPSI + z],     psi[z],     iB0);
                iB1 = fmaf(Msm[(j + 1) * DPSI + 4 + z], psi[4 + z], iB1);
            }
            c0 = fmaf(__ldg(&Wphi[j * S_DIM + s]),       iA0 + iA1, c0);
            c1 = fmaf(__ldg(&Wphi[(j + 1) * S_DIM + s]), iB0 + iB1, c1);
        }
        c = c0 + c1;
    }
    Ctmp[tid] = c;
    __syncthreads();

    // --- store padded [17][8]; pad column = 0 ---
    if (tid < CPS) {
        const int row = tid >> 3;
        const int col = tid & 7;
        float v = 0.f;
        if (col < A_DIM) {
            const int o = row * A_DIM + col;
            v = (Ctmp[4 * o] + Ctmp[4 * o + 1]) + (Ctmp[4 * o + 2] + Ctmp[4 * o + 3]);
        }
        g_Cpart[p * CPS + tid] = v;
    }
}

// ---------------------------------------------------------------------------
// Kernel 2 (PDL secondary): out[b] = state[b,:] * C * action[b,:]
// Order: front-batch 7 LDG.128 into registers -> gridDepSync (waits k1 while
// loads fly) -> C-reduce from L2 -> STS -> one barrier -> compute.
// ---------------------------------------------------------------------------
__global__ __launch_bounds__(256)
void k_main(const float* __restrict__ state,   // [B,17]
            const float* __restrict__ action,  // [B,7]
            float* __restrict__ out)           // [B]
{
    __shared__ __align__(16) float Ss[TILE * S_DIM];   // 4352 floats
    __shared__ __align__(16) float As[TILE * A_DIM];   // 1792 floats
    __shared__ __align__(16) float Csm[CPS];           // padded [17][8]

    const int tid = threadIdx.x;
    const int bx  = blockIdx.x;

    // --- front-batch ALL staging loads into registers ---
    const float4* S4 = reinterpret_cast<const float4*>(state)  + (size_t)bx * 1088;
    const float4* A4 = reinterpret_cast<const float4*>(action) + (size_t)bx * 448;
    float4 s0 = S4[tid];
    float4 s1 = S4[tid + 256];
    float4 s2 = S4[tid + 512];
    float4 s3 = S4[tid + 768];
    float4 s4 = make_float4(0.f,0.f,0.f,0.f);
    if (tid < 64) s4 = S4[tid + 1024];
    float4 a0 = A4[tid];
    float4 a1 = make_float4(0.f,0.f,0.f,0.f);
    if (tid < 192) a1 = A4[tid + 256];

    // --- wait for k1 while the loads above are still in flight ---
    cudaGridDependencySynchronize();

    // --- partial-C reduce: 34 threads x 32 float4 L2 loads, fixed order ---
    if (tid < CPS4) {
        const float4* P4 = reinterpret_cast<const float4*>(g_Cpart);
        float4 cred = make_float4(0.f, 0.f, 0.f, 0.f);
#pragma unroll 8
        for (int pp = 0; pp < NPART; pp++) {
            const float4 x = P4[pp * CPS4 + tid];
            cred.x += x.x; cred.y += x.y; cred.z += x.z; cred.w += x.w;
        }
        reinterpret_cast<float4*>(Csm)[tid] = cred;
    }

    // --- park tiles in smem ---
    {
        float4* D = reinterpret_cast<float4*>(Ss);
        D[tid]       = s0;
        D[tid + 256] = s1;
        D[tid + 512] = s2;
        D[tid + 768] = s3;
        if (tid < 64) D[tid + 1024] = s4;
        float4* E = reinterpret_cast<float4*>(As);
        E[tid] = a0;
        if (tid < 192) E[tid + 256] = a1;
    }
    __syncthreads();

    // --- per-sample bilinear form ---
    const float* av = As + tid * A_DIM;    // lane stride 7: conflict-free
    const float v0 = av[0], v1 = av[1], v2 = av[2], v3 = av[3];
    const float v4 = av[4], v5 = av[5], v6 = av[6];

    const float4* C4 = reinterpret_cast<const float4*>(Csm);
    const float*  st = Ss + tid * S_DIM;   // lane stride 17: conflict-free

    float r = 0.f;
#pragma unroll
    for (int s = 0; s < S_DIM; s++) {
        const float4 c0 = C4[2 * s];       // broadcast LDS.128
        const float4 c1 = C4[2 * s + 1];   // C[s][4..6], pad
        float t;
        t = c0.x * v0;
        t = fmaf(c0.y, v1, t);
        t = fmaf(c0.z, v2, t);
        t = fmaf(c0.w, v3, t);
        t = fmaf(c1.x, v4, t);
        t = fmaf(c1.y, v5, t);
        t = fmaf(c1.z, v6, t);
        r = fmaf(st[s], t, r);
    }

    out[bx * TILE + tid] = r;
}

// ---------------------------------------------------------------------------
extern "C" void kernel_launch(void* const* d_in, const int* in_sizes, int n_in,
                              void* d_out, int out_size)
{
    const float* state  = (const float*)d_in[0];
    const float* action = (const float*)d_in[1];
    const float* Wphi   = (const float*)d_in[2];
    const float* Wpsi   = (const float*)d_in[3];
    const float* K      = (const float*)d_in[4];
    const float* wlin   = (const float*)d_in[5];
    float* out = (float*)d_out;

    k_partialC<<<NPART, 512>>>(Wphi, Wpsi, K, wlin);

    // PDL secondary launch: overlap with k_partialC.
    cudaLaunchConfig_t cfg = {};
    cfg.gridDim  = dim3(NBLK_MAIN, 1, 1);
    cfg.blockDim = dim3(256, 1, 1);
    cfg.dynamicSmemBytes = 0;
    cfg.stream = 0;
    cudaLaunchAttribute attr[1];
    attr[0].id = cudaLaunchAttributeProgrammaticStreamSerialization;
    attr[0].val.programmaticStreamSerializationAllowed = 1;
    cfg.attrs    = attr;
    cfg.numAttrs = 1;
    cudaLaunchKernelEx(&cfg, k_main, state, action, out);
}

// round 10
// speedup vs baseline: 1.4276x; 1.4276x over previous
#include <cuda_runtime.h>
#include <cstdint>

// Problem constants (fixed by the dataset)
#define B_TOTAL   131072
#define S_DIM     17
#define A_DIM     7
#define DPHI      128
#define DPSI      8

#define NPART     32                  // partial-C blocks
#define I_PER     (DPHI / NPART)      // 4 i-values per block
#define CPS       136                 // padded [17][8] floats per partial
#define CPS4      34                  // ... as float4

#define TILE      512                 // samples per k_main block
#define NBLK_MAIN (B_TOTAL / TILE)    // 512 blocks
#define NTHR      128                 // k_main threads (4 samples/thread)

// dynamic smem layout (floats): Ss[512*17] | As[512*7] | Csm[136]
#define OFF_AS    (TILE * S_DIM)              // 8704
#define OFF_CS    (OFF_AS + TILE * A_DIM)     // 12288
#define SMEM_BYTES ((OFF_CS + CPS) * 4)       // 49696

// Per-block partial C matrices, padded [17][8] (pad col written as 0).
__device__ float g_Cpart[NPART * CPS];

// 16-byte async copy global->shared, fire-and-forget.
__device__ __forceinline__ void cp16(uint32_t dst_smem, const void* src) {
    asm volatile("cp.async.cg.shared.global [%0], [%1], 16;"
                 :: "r"(dst_smem), "l"(src) : "memory");
}
__device__ __forceinline__ void cp_async_wait_all() {
    asm volatile("cp.async.wait_all;" ::: "memory");
}

// ---------------------------------------------------------------------------
// Kernel 1 (R8-proven, 256 thr, fence-free): block p computes partial C over
// i in [p*I_PER,(p+1)*I_PER). Implicit PDL completion trigger covers writes.
// ---------------------------------------------------------------------------
__global__ __launch_bounds__(256)
void k_partialC(const float* __restrict__ Wphi,   // [128,17]
                const float* __restrict__ Wpsi,   // [8,7]
                const float* __restrict__ K,      // [128,128,8]
                const float* __restrict__ wlin)   // [1,128]
{
    __shared__ float Msm[DPHI * DPSI];   // 1024 floats, layout j*8+z
    __shared__ float Ctmp[256];

    const int p   = blockIdx.x;
    const int tid = threadIdx.x;         // 256 threads

    // --- M partial: each thread owns one float4 of the 1024 floats ---
    {
        const float4* K4 = reinterpret_cast<const float4*>(K);
        float4 acc = make_float4(0.f, 0.f, 0.f, 0.f);
#pragma unroll
        for (int ii = 0; ii < I_PER; ii++) {
            const int i = p * I_PER + ii;
            const float w = __ldg(&wlin[i]);
            const float4 kv = K4[i * 256 + tid];
            acc.x = fmaf(w, kv.x, acc.x);
            acc.y = fmaf(w, kv.y, acc.y);
            acc.z = fmaf(w, kv.z, acc.z);
            acc.w = fmaf(w, kv.w, acc.w);
        }
        reinterpret_cast<float4*>(Msm)[tid] = acc;
    }
    __syncthreads();

    // --- C partial: 2 threads per (s,a), each covering half the j range ---
    float c = 0.f;
    if (tid < 2 * S_DIM * A_DIM) {       // 238 active threads
        const int o    = tid >> 1;
        const int half = tid & 1;
        const int s = o / A_DIM;
        const int a = o - s * A_DIM;

        float psi[DPSI];
#pragma unroll
        for (int z = 0; z < DPSI; z++) psi[z] = __ldg(&Wpsi[z * A_DIM + a]);

        const int j0 = half * 64;
#pragma unroll 4
        for (int j = j0; j < j0 + 64; j++) {
            float inner = 0.f;
#pragma unroll
            for (int z = 0; z < DPSI; z++)
                inner = fmaf(Msm[j * DPSI + z], psi[z], inner);
            c = fmaf(__ldg(&Wphi[j * S_DIM + s]), inner, c);
        }
    }
    Ctmp[tid] = c;
    __syncthreads();

    // --- store padded [17][8]; pad column = 0 ---
    if (tid < CPS) {
        const int row = tid >> 3;
        const int col = tid & 7;
        float v = 0.f;
        if (col < A_DIM) {
            const int o = row * A_DIM + col;
            v = Ctmp[2 * o] + Ctmp[2 * o + 1];
        }
        g_Cpart[p * CPS + tid] = v;
    }
}

// ---------------------------------------------------------------------------
// Kernel 2 (PDL secondary): out[b] = state[b,:] * C * action[b,:]
// 512 blocks x 128 thr, TILE=512 (4 samples/thread). 24 cp.async copies per
// thread (17 state + 7 action, all full rounds) -> ~196 KB/SM in flight.
// C-row loads amortized across 4 samples in the compute phase.
// ---------------------------------------------------------------------------
__global__ __launch_bounds__(NTHR)
void k_main(const float* __restrict__ state,   // [B,17]
            const float* __restrict__ action,  // [B,7]
            float* __restrict__ out)           // [B]
{
    extern __shared__ __align__(16) float sbuf[];
    float* Ss  = sbuf;             // [512][17]
    float* As  = sbuf + OFF_AS;    // [512][7]
    float* Csm = sbuf + OFF_CS;    // padded [17][8]

    const int tid = threadIdx.x;
    const int bx  = blockIdx.x;

    // --- issue ALL 24 staging copies asynchronously ---
    {
        const float4* S4 = reinterpret_cast<const float4*>(state)  + (size_t)bx * (TILE * S_DIM / 4);
        const float4* A4 = reinterpret_cast<const float4*>(action) + (size_t)bx * (TILE * A_DIM / 4);
        uint32_t Ds = (uint32_t)__cvta_generic_to_shared(Ss);
        uint32_t Da = (uint32_t)__cvta_generic_to_shared(As);
#pragma unroll
        for (int k = 0; k < 17; k++)           // 17*128 = 2176 float4
            cp16(Ds + (tid + k * NTHR) * 16, S4 + tid + k * NTHR);
#pragma unroll
        for (int k = 0; k < 7; k++)            // 7*128 = 896 float4
            cp16(Da + (tid + k * NTHR) * 16, A4 + tid + k * NTHR);
    }

    // --- wait for k1 while the copies above are in flight ---
    cudaGridDependencySynchronize();

    // --- partial-C reduce: 34 threads x 32 float4 L2 loads, fixed order ---
    if (tid < CPS4) {
        const float4* P4 = reinterpret_cast<const float4*>(g_Cpart);
        float4 cred = make_float4(0.f, 0.f, 0.f, 0.f);
#pragma unroll 8
        for (int pp = 0; pp < NPART; pp++) {
            const float4 x = P4[pp * CPS4 + tid];
            cred.x += x.x; cred.y += x.y; cred.z += x.z; cred.w += x.w;
        }
        reinterpret_cast<float4*>(Csm)[tid] = cred;
    }

    cp_async_wait_all();
    __syncthreads();

    // --- 4 samples per thread: local rows tid, tid+128, tid+256, tid+384 ---
    float av[4][A_DIM];
#pragma unroll
    for (int q = 0; q < 4; q++) {
        const float* a = As + (tid + q * NTHR) * A_DIM;  // stride 7: conflict-free
#pragma unroll
        for (int z = 0; z < A_DIM; z++) av[q][z] = a[z];
    }

    const float4* C4 = reinterpret_cast<const float4*>(Csm);
    float acc0 = 0.f, acc1 = 0.f, acc2 = 0.f, acc3 = 0.f;

#pragma unroll
    for (int s = 0; s < S_DIM; s++) {
        const float4 c0 = C4[2 * s];       // broadcast LDS.128
        const float4 c1 = C4[2 * s + 1];   // C[s][4..6], pad

        float t0, t1, t2, t3;
        t0 = c0.x * av[0][0];  t1 = c0.x * av[1][0];
        t2 = c0.x * av[2][0];  t3 = c0.x * av[3][0];
        t0 = fmaf(c0.y, av[0][1], t0);  t1 = fmaf(c0.y, av[1][1], t1);
        t2 = fmaf(c0.y, av[2][1], t2);  t3 = fmaf(c0.y, av[3][1], t3);
        t0 = fmaf(c0.z, av[0][2], t0);  t1 = fmaf(c0.z, av[1][2], t1);
        t2 = fmaf(c0.z, av[2][2], t2);  t3 = fmaf(c0.z, av[3][2], t3);
        t0 = fmaf(c0.w, av[0][3], t0);  t1 = fmaf(c0.w, av[1][3], t1);
        t2 = fmaf(c0.w, av[2][3], t2);  t3 = fmaf(c0.w, av[3][3], t3);
        t0 = fmaf(c1.x, av[0][4], t0);  t1 = fmaf(c1.x, av[1][4], t1);
        t2 = fmaf(c1.x, av[2][4], t2);  t3 = fmaf(c1.x, av[3][4], t3);
        t0 = fmaf(c1.y, av[0][5], t0);  t1 = fmaf(c1.y, av[1][5], t1);
        t2 = fmaf(c1.y, av[2][5], t2);  t3 = fmaf(c1.y, av[3][5], t3);
        t0 = fmaf(c1.z, av[0][6], t0);  t1 = fmaf(c1.z, av[1][6], t1);
        t2 = fmaf(c1.z, av[2][6], t2);  t3 = fmaf(c1.z, av[3][6], t3);

        acc0 = fmaf(Ss[(tid          ) * S_DIM + s], t0, acc0);
        acc1 = fmaf(Ss[(tid + 1*NTHR) * S_DIM + s], t1, acc1);
        acc2 = fmaf(Ss[(tid + 2*NTHR) * S_DIM + s], t2, acc2);
        acc3 = fmaf(Ss[(tid + 3*NTHR) * S_DIM + s], t3, acc3);
    }

    float* ob = out + (size_t)bx * TILE;
    ob[tid          ] = acc0;
    ob[tid + 1*NTHR] = acc1;
    ob[tid + 2*NTHR] = acc2;
    ob[tid + 3*NTHR] = acc3;
}

// ---------------------------------------------------------------------------
extern "C" void kernel_launch(void* const* d_in, const int* in_sizes, int n_in,
                              void* d_out, int out_size)
{
    const float* state  = (const float*)d_in[0];
    const float* action = (const float*)d_in[1];
    const float* Wphi   = (const float*)d_in[2];
    const float* Wpsi   = (const float*)d_in[3];
    const float* K      = (const float*)d_in[4];
    const float* wlin   = (const float*)d_in[5];
    float* out = (float*)d_out;

    // Allow >48KB dynamic smem for k_main (attribute set, not an allocation).
    static bool attr_done = false;
    if (!attr_done) {
        cudaFuncSetAttribute(k_main,
                             cudaFuncAttributeMaxDynamicSharedMemorySize,
                             SMEM_BYTES);
        attr_done = true;
    }

    k_partialC<<<NPART, 256>>>(Wphi, Wpsi, K, wlin);

    // PDL secondary launch: overlap with k_partialC.
    cudaLaunchConfig_t cfg = {};
    cfg.gridDim  = dim3(NBLK_MAIN, 1, 1);
    cfg.blockDim = dim3(NTHR, 1, 1);
    cfg.dynamicSmemBytes = SMEM_BYTES;
    cfg.stream = 0;
    cudaLaunchAttribute attr[1];
    attr[0].id = cudaLaunchAttributeProgrammaticStreamSerialization;
    attr[0].val.programmaticStreamSerializationAllowed = 1;
    cfg.attrs    = attr;
    cfg.numAttrs = 1;
    cudaLaunchKernelEx(&cfg, k_main, state, action, out);
}